// round 5
// baseline (speedup 1.0000x reference)
#include <cuda_runtime.h>
#include <math.h>

// ---------------- problem constants ----------------
#define BATCH      32768
#define TILE_B     64
#define NTHREADS   256
#define HORIZON_T  64

// smem layout (in floats)
#define OFF_AH0   0
#define OFF_AH1   16384                 // 64*256
#define OFF_BSH   32768                 // 32 kp * 256 n * (ull) = 16384 floats
#define OFF_W1    49152                 // 8 kp * 256 n * (ull) = 4096 floats
#define OFF_WMU   53248                 // 2*256
#define OFF_B1    53760
#define OFF_B2    54016
#define OFF_B3    54272
#define OFF_BMU   54528
#define SMEM_FLOATS 54532
#define SMEM_BYTES  (SMEM_FLOATS * 4)

// ---------------- packed f32x2 helpers ----------------
__device__ __forceinline__ unsigned long long pk2(float x, float y) {
    unsigned long long r;
    asm("mov.b64 %0, {%1, %2};" : "=l"(r) : "f"(x), "f"(y));
    return r;
}
__device__ __forceinline__ void upk2(unsigned long long v, float& x, float& y) {
    asm("mov.b64 {%0, %1}, %2;" : "=f"(x), "=f"(y) : "l"(v));
}
__device__ __forceinline__ void ffma2(unsigned long long& d,
                                      unsigned long long a,
                                      unsigned long long b) {
    asm("fma.rn.f32x2 %0, %1, %2, %0;" : "+l"(d) : "l"(a), "l"(b));
}

// ---------------- GEMM tile: 64(m) x 256(n), acc lanes = (even k, odd k) ----
// warp w owns m rows [8w, 8w+8); lane l owns n cols {l, l+32, ..., l+224}
// A must already be offset to the k-chunk base (column 0 of this chunk).
template <int KPC, int APITCH>
__device__ __forceinline__ void mma_tile(unsigned long long acc[8][8],
                                         const float* __restrict__ A,
                                         const unsigned long long* __restrict__ B,
                                         int w, int l) {
    const float* Aw = A + (w * 8) * APITCH;
#pragma unroll 2
    for (int kp = 0; kp < KPC; ++kp) {
        unsigned long long areg[8], breg[8];
#pragma unroll
        for (int i = 0; i < 8; ++i)
            areg[i] = *reinterpret_cast<const unsigned long long*>(Aw + i * APITCH + 2 * kp);
        const unsigned long long* Brow = B + kp * 256 + l;
#pragma unroll
        for (int j = 0; j < 8; ++j) breg[j] = Brow[32 * j];
#pragma unroll
        for (int i = 0; i < 8; ++i)
#pragma unroll
            for (int j = 0; j < 8; ++j) ffma2(acc[i][j], areg[i], breg[j]);
    }
}

__device__ __forceinline__ void zero_acc(unsigned long long acc[8][8]) {
#pragma unroll
    for (int i = 0; i < 8; ++i)
#pragma unroll
        for (int j = 0; j < 8; ++j) acc[i][j] = 0ull;
}

// epilogue: c = relu(lo+hi + bias[n]) -> out (pitch 256)
__device__ __forceinline__ void epilogue_relu(unsigned long long acc[8][8],
                                              float* __restrict__ out,
                                              const float* __restrict__ bias,
                                              int w, int l) {
#pragma unroll
    for (int i = 0; i < 8; ++i) {
        float* orow = out + (w * 8 + i) * 256;
#pragma unroll
        for (int j = 0; j < 8; ++j) {
            int n = l + 32 * j;
            float x, y;
            upk2(acc[i][j], x, y);
            float c = x + y + bias[n];
            orow[n] = fmaxf(c, 0.0f);
        }
    }
}

// stage a 64-k chunk of a 256x256 weight (k-major) as k-pairs: Bsh[kp][n]
__device__ __forceinline__ void stageB(unsigned long long* __restrict__ Bsh,
                                       const float* __restrict__ W,
                                       int k0, int tid) {
#pragma unroll
    for (int i = 0; i < 32; ++i) {
        int k = k0 + 2 * i;
        float x = W[k * 256 + tid];
        float y = W[(k + 1) * 256 + tid];
        Bsh[i * 256 + tid] = pk2(x, y);
    }
}

// ---------------- main kernel ----------------
__global__ void __launch_bounds__(NTHREADS, 1)
rollout_kernel(const float* __restrict__ pos0, const float* __restrict__ wind,
               const float* __restrict__ w1, const float* __restrict__ b1,
               const float* __restrict__ w2, const float* __restrict__ b2,
               const float* __restrict__ w3, const float* __restrict__ b3,
               const float* __restrict__ wmu, const float* __restrict__ bmu,
               float* __restrict__ out) {
    extern __shared__ float smem[];
    float* Ah0 = smem + OFF_AH0;
    float* Ah1 = smem + OFF_AH1;
    unsigned long long* Bsh  = reinterpret_cast<unsigned long long*>(smem + OFF_BSH);
    unsigned long long* W1sh = reinterpret_cast<unsigned long long*>(smem + OFF_W1);
    float* wmu_s = smem + OFF_WMU;
    float* b1s = smem + OFF_B1;
    float* b2s = smem + OFF_B2;
    float* b3s = smem + OFF_B3;
    float* bmu_s = smem + OFF_BMU;

    const int tid = threadIdx.x;
    const int w = tid >> 5;
    const int l = tid & 31;

    // ---- one-time staging of small constants ----
    b1s[tid] = b1[tid];
    b2s[tid] = b2[tid];
    b3s[tid] = b3[tid];
    for (int idx = tid; idx < 512; idx += NTHREADS) {
        int c = idx >> 8, k = idx & 255;
        wmu_s[idx] = wmu[k * 2 + c];  // wmu_s[c][k]
    }
    if (tid < 2) bmu_s[tid] = bmu[tid];
#pragma unroll
    for (int i = 0; i < 8; ++i) {  // w1: 13x256 padded to K=16, as k-pairs
        int k0 = 2 * i, k1 = 2 * i + 1;
        float x = (k0 < 13) ? w1[k0 * 256 + tid] : 0.0f;
        float y = (k1 < 13) ? w1[k1 * 256 + tid] : 0.0f;
        W1sh[i * 256 + tid] = pk2(x, y);
    }

    // ---- per-batch-element persistent state (even tids < 128 own element m) ----
    const bool owner = (tid < 128) && ((tid & 1) == 0);
    const int m = tid >> 1;
    const int bidx = blockIdx.x * TILE_B + m;
    float px = 0.f, py = 0.f, wx = 0.f, wy = 0.f;
    float msafe = -INFINITY, ssafe = 0.f, mreach = -INFINITY, sreach = 0.f;
    if (owner) {
        px = pos0[2 * bidx]; py = pos0[2 * bidx + 1];
        wx = wind[2 * bidx]; wy = wind[2 * bidx + 1];
    }

    const float ox0 = 1.75f, oy0 = 1.75f, r0 = 0.38f;
    const float ox1 = 1.75f, oy1 = 3.75f, r1 = 0.42f;
    const float ox2 = 3.75f, oy2 = 2.00f, r2 = 0.34f;

    __syncthreads();

    unsigned long long acc[8][8];

    for (int t = 0; t < HORIZON_T; ++t) {
        // ---- observations -> Ah0 (pitch 16, cols 13..15 zero) ----
        if (owner) {
            float* o = Ah0 + m * 16;
            o[0] = px * 0.1f;
            o[1] = py * 0.1f;
            o[2] = (4.0f - px) * 0.1f;
            o[3] = (3.0f - py) * 0.1f;
            float dx0 = px - ox0, dy0 = py - oy0;
            float dx1 = px - ox1, dy1 = py - oy1;
            float dx2 = px - ox2, dy2 = py - oy2;
            float d0 = sqrtf(dx0 * dx0 + dy0 * dy0 + 1e-9f);
            float d1 = sqrtf(dx1 * dx1 + dy1 * dy1 + 1e-9f);
            float d2 = sqrtf(dx2 * dx2 + dy2 * dy2 + 1e-9f);
            o[4] = -dx0 * 0.1f; o[5] = -dy0 * 0.1f;
            o[6] = -dx1 * 0.1f; o[7] = -dy1 * 0.1f;
            o[8] = -dx2 * 0.1f; o[9] = -dy2 * 0.1f;
            o[10] = d0 - r0; o[11] = d1 - r1; o[12] = d2 - r2;
            o[13] = 0.f; o[14] = 0.f; o[15] = 0.f;
        }
        __syncthreads();

        // ---- layer 1: (64x16) @ (16x256) ----
        zero_acc(acc);
        mma_tile<8, 16>(acc, Ah0, W1sh, w, l);
        epilogue_relu(acc, Ah1, b1s, w, l);
        __syncthreads();

        // ---- layer 2: (64x256) @ (256x256), 4 K-chunks ----
        zero_acc(acc);
#pragma unroll 1
        for (int c = 0; c < 4; ++c) {
            stageB(Bsh, w2, c * 64, tid);
            __syncthreads();
            mma_tile<32, 256>(acc, Ah1 + c * 64, Bsh, w, l);   // <-- A advances with k-chunk
            __syncthreads();
        }
        epilogue_relu(acc, Ah0, b2s, w, l);

        // ---- layer 3 ----
        zero_acc(acc);
#pragma unroll 1
        for (int c = 0; c < 4; ++c) {
            stageB(Bsh, w3, c * 64, tid);
            __syncthreads();
            mma_tile<32, 256>(acc, Ah0 + c * 64, Bsh, w, l);   // <-- A advances with k-chunk
            __syncthreads();
        }
        epilogue_relu(acc, Ah1, b3s, w, l);
        __syncthreads();

        // ---- layer 4: actions = clip(h3 @ wmu + bmu), threads 0..127 ----
        float act0 = 0.f, act1 = 0.f;
        if (tid < 128) {
            int mm = tid >> 1, cc = tid & 1;
            const float4* hrow = reinterpret_cast<const float4*>(Ah1 + mm * 256);
            const float4* wrow = reinterpret_cast<const float4*>(wmu_s + cc * 256);
            float accd = bmu_s[cc];
#pragma unroll 8
            for (int ii = 0; ii < 64; ++ii) {
                int idx = (ii + mm) & 63;  // stagger to dodge bank conflicts
                float4 h4 = hrow[idx];
                float4 w4 = wrow[idx];
                accd = fmaf(h4.x, w4.x, accd);
                accd = fmaf(h4.y, w4.y, accd);
                accd = fmaf(h4.z, w4.z, accd);
                accd = fmaf(h4.w, w4.w, accd);
            }
            float other = __shfl_xor_sync(0xffffffffu, accd, 1);
            if (cc == 0) { act0 = accd; act1 = other; }
        }

        // ---- dynamics + streaming STREL stats ----
        if (owner) {
            float ax = fminf(fmaxf(act0, -1.0f), 1.0f);
            float ay = fminf(fmaxf(act1, -1.0f), 1.0f);
            float vx = 2.0f * ax + wx;
            float vy = 2.0f * ay + wy;
#pragma unroll
            for (int s = 0; s < 4; ++s) {
                px = fminf(fmaxf(px + 0.0625f * vx, -4.0f), 10.0f);
                py = fminf(fmaxf(py + 0.0625f * vy, -4.0f), 10.0f);
            }
            // spatial smooth-min clearance (beta=50)
            float dx0 = px - ox0, dy0 = py - oy0;
            float dx1 = px - ox1, dy1 = py - oy1;
            float dx2 = px - ox2, dy2 = py - oy2;
            float c0 = sqrtf(dx0 * dx0 + dy0 * dy0 + 1e-9f) - r0;
            float c1 = sqrtf(dx1 * dx1 + dy1 * dy1 + 1e-9f) - r1;
            float c2 = sqrtf(dx2 * dx2 + dy2 * dy2 + 1e-9f) - r2;
            float v0 = -50.0f * c0, v1 = -50.0f * c1, v2 = -50.0f * c2;
            float vm = fmaxf(v0, fmaxf(v1, v2));
            float lse = vm + logf(expf(v0 - vm) + expf(v1 - vm) + expf(v2 - vm));
            float safe = -lse / 50.0f;
            // streaming LSE of -8*safe (for Always)
            float vs = -8.0f * safe;
            if (vs > msafe) { ssafe = ssafe * expf(msafe - vs) + 1.0f; msafe = vs; }
            else            { ssafe += expf(vs - msafe); }
            // streaming LSE of 8*(tol - goal_dist) (for Eventually)
            float gdx = px - 4.0f, gdy = py - 3.0f;
            float gd = sqrtf(gdx * gdx + gdy * gdy + 1e-9f);
            float vr = 8.0f * (0.45f - gd);
            if (vr > mreach) { sreach = sreach * expf(mreach - vr) + 1.0f; mreach = vr; }
            else             { sreach += expf(vr - mreach); }
        }
        // loop-top __syncthreads orders obs writes vs layer-1 reads
    }

    if (owner) {
        float rs = -(msafe + logf(ssafe)) * 0.125f;   // rho_safe
        float rr =  (mreach + logf(sreach)) * 0.125f; // rho_reach
        float u0 = -8.0f * rs, u1 = -8.0f * rr;
        float um = fmaxf(u0, u1);
        float rho = -(um + logf(expf(u0 - um) + expf(u1 - um))) * 0.125f;
        out[bidx] = rho;
    }
}

// ---------------- launch ----------------
extern "C" void kernel_launch(void* const* d_in, const int* in_sizes, int n_in,
                              void* d_out, int out_size) {
    const float* pos0 = (const float*)d_in[0];
    const float* wind = (const float*)d_in[1];
    const float* w1   = (const float*)d_in[2];
    const float* b1   = (const float*)d_in[3];
    const float* w2   = (const float*)d_in[4];
    const float* b2   = (const float*)d_in[5];
    const float* w3   = (const float*)d_in[6];
    const float* b3   = (const float*)d_in[7];
    const float* wmu  = (const float*)d_in[8];
    const float* bmu  = (const float*)d_in[9];
    float* out = (float*)d_out;

    cudaFuncSetAttribute(rollout_kernel,
                         cudaFuncAttributeMaxDynamicSharedMemorySize, SMEM_BYTES);

    int B = in_sizes[0] / 2;           // 32768
    int grid = B / TILE_B;             // 512
    rollout_kernel<<<grid, NTHREADS, SMEM_BYTES>>>(pos0, wind, w1, b1, w2, b2,
                                                   w3, b3, wmu, bmu, out);
}